// round 13
// baseline (speedup 1.0000x reference)
#include <cuda_runtime.h>
#include <math.h>

#define H        64
#define NZ       120
#define NLAYERS  4
#define DIMH     256
#define DIMG     65536

#define TB_BLKS  120            // table blocks in kA
#define HB_BLKS  256            // histogram blocks in kA
#define GRIDA    (TB_BLKS + HB_BLKS)
#define ROWW     65             // padded row width (words) per bin
#define GRIDB    257

// Scratch (no allocations allowed)
__device__ int      d_hist[NZ];         // global histogram (int atomics =
                                        // deterministic; kB phase-2 re-zeroes)
__device__ float    d_ftab[NZ * H];     // UNWEIGHTED post-layer table f_z
__device__ float    d_gbuf[DIMG];       // unsymmetrized g
__device__ unsigned d_cnt = 0;          // monotonic barrier ticket counter:
                                        // each kB launch consumes exactly
                                        // GRIDB tickets -> replay-deterministic

// ---------------------------------------------------------------------------
// kA (unchanged from R12 -- 13.2us -> 7.0us, chain fixes verified):
//   blocks [0,120):    f_z table, k split 4 ways across 256 threads
//   blocks [120,376):  histogram via private byte counters, batched loads
// ---------------------------------------------------------------------------
__global__ void __launch_bounds__(256)
kA(const int* __restrict__ Z, int n,
   const float* __restrict__ embed, const float* __restrict__ W_tp) {
    const int t   = threadIdx.x;
    const int bid = blockIdx.x;

    if (bid < TB_BLKS) {
        __shared__ float xs[H];
        __shared__ float red[256];
        const int j = t & 63, p = t >> 6;
        if (t < H) xs[t] = embed[bid * H + t];
        __syncthreads();

        #pragma unroll
        for (int l = 0; l < NLAYERS; ++l) {
            const float* __restrict__ W = W_tp + l * H * H + p * 16 * H;
            float a = 0.f;
            #pragma unroll
            for (int kk = 0; kk < 16; ++kk)
                a = fmaf(xs[p * 16 + kk], W[kk * H + j], a);
            red[t] = a;
            __syncthreads();
            if (t < H) {
                float s = (red[t] + red[t + 64] + red[t + 128] + red[t + 192])
                          * 0.125f;                 // INV_SQRT_H = 1/sqrt(64)
                xs[t] = s / (1.f + expf(-s));       // silu
            }
            __syncthreads();
        }
        if (t < H) d_ftab[bid * H + t] = xs[t];
    } else {
        __shared__ unsigned int cnt32[NZ * ROWW];   // 31,200 B
        unsigned char* cnt8 = (unsigned char*)cnt32;
        const int hb = bid - TB_BLKS;

        for (int i = t; i < NZ * ROWW; i += 256) cnt32[i] = 0;

        // dtype sniff, warp-parallel (Z may be int32 or int64 per JAX x64)
        const int lane = t & 31;
        const int probe = Z[2 * lane + 1];
        const unsigned nzmask = __ballot_sync(0xffffffffu, probe != 0);
        const bool is64 = (nzmask == 0u);
        __syncthreads();

        const int4* __restrict__ Z4 = (const int4*)Z;
        const int tid = hb * 256 + t;

#define BUMP4(v) { cnt8[(v).x * 260 + t]++; cnt8[(v).y * 260 + t]++; \
                   cnt8[(v).z * 260 + t]++; cnt8[(v).w * 260 + t]++; }
#define BUMP2(v) { cnt8[(v).x * 260 + t]++; cnt8[(v).z * 260 + t]++; }

        if (!is64) {
            const int n4 = n >> 2;
            const int base = tid * 4;
            if (base + 3 < n4) {
                int4 v0 = Z4[base], v1 = Z4[base + 1],
                     v2 = Z4[base + 2], v3 = Z4[base + 3];   // MLP = 4
                BUMP4(v0) BUMP4(v1) BUMP4(v2) BUMP4(v3)
            } else {
                for (int i = base; i < n4; ++i) { int4 v = Z4[i]; BUMP4(v) }
            }
        } else {
            const int n2 = n >> 1;
            const int base = tid * 8;
            if (base + 7 < n2) {
                int4 v0 = Z4[base],     v1 = Z4[base + 1],
                     v2 = Z4[base + 2], v3 = Z4[base + 3],
                     v4 = Z4[base + 4], v5 = Z4[base + 5],
                     v6 = Z4[base + 6], v7 = Z4[base + 7];   // MLP = 8
                BUMP2(v0) BUMP2(v1) BUMP2(v2) BUMP2(v3)
                BUMP2(v4) BUMP2(v5) BUMP2(v6) BUMP2(v7)
            } else {
                for (int i = base; i < n2; ++i) { int4 v = Z4[i]; BUMP2(v) }
            }
        }
#undef BUMP4
#undef BUMP2
        __syncthreads();

        if (t < NZ) {
            unsigned int acc = 0;
            #pragma unroll
            for (int w = 0; w < ROWW; ++w)
                acc = __dp4a(cnt32[t * ROWW + w], 0x01010101u, acc);
            atomicAdd(&d_hist[t], (int)acc);
        }
    }
}

// ---------------------------------------------------------------------------
// kB = old k3 + k4 fused with ONE ticket barrier (saves a launch boundary).
// Phase 1: gf reduce (redundant per block, L2-hot) ->
//          blocks 0..255: g slice = gf @ w_g + b_g  (w_g L2-resident, ~1us)
//          block 256:     h matvec + h symmetrize -> out[0:256]
// Barrier: monotonic tickets; target = next multiple of GRIDB. Deterministic
//          across graph replays (each launch consumes exactly GRIDB tickets).
// Phase 2: blocks 0..255: 8-fold sym of d_gbuf -> out[256:]; block 256
//          re-zeroes d_hist (all phase-1 reads of d_hist precede the barrier).
// ---------------------------------------------------------------------------
__global__ void __launch_bounds__(256)
kB(const float* __restrict__ w_g, const float* __restrict__ b_g,
   const float* __restrict__ w_h, const float* __restrict__ b_h,
   float* __restrict__ out) {
    __shared__ float scnt[NZ];
    __shared__ float gf[H];
    __shared__ float red[DIMH];
    const int t = threadIdx.x;

    if (t < NZ) scnt[t] = (float)d_hist[t];
    __syncthreads();

    {   // gf[j] = sum_z scnt[z] * f_z[j]; 4 strips of 30 z's per feature j
        const int j = t & 63, p = t >> 6;
        float s = 0.f;
        #pragma unroll
        for (int z = p * 30; z < p * 30 + 30; ++z)
            s = fmaf(scnt[z], d_ftab[z * H + j], s);
        red[t] = s;
        __syncthreads();
        if (t < H) gf[t] = red[t] + red[t + 64] + red[t + 128] + red[t + 192];
        __syncthreads();
    }

    if (blockIdx.x < 256) {
        const int i = blockIdx.x * 256 + t;
        float acc = b_g[i];
        #pragma unroll
        for (int k = 0; k < H; ++k)
            acc = fmaf(gf[k], w_g[k * DIMG + i], acc);
        d_gbuf[i] = acc;
    } else {
        float acc = b_h[t];
        #pragma unroll
        for (int k = 0; k < H; ++k)
            acc = fmaf(gf[k], w_h[k * DIMH + t], acc);
        red[t] = acc;
        __syncthreads();
        const int i = t >> 4, j = t & 15;
        out[t] = 0.5f * (red[i * 16 + j] + red[j * 16 + i]);
    }

    // ---- device-wide ticket barrier (one per kB launch) ----
    __threadfence();                        // publish d_gbuf writes
    __syncthreads();                        // whole block arrived
    if (t == 0) {
        unsigned my = atomicAdd(&d_cnt, 1u);
        unsigned target = (my / GRIDB + 1u) * GRIDB;
        while (atomicAdd(&d_cnt, 0u) < target) { }
    }
    __syncthreads();
    __threadfence();                        // acquire peers' d_gbuf writes

    // ---- phase 2 ----
    if (blockIdx.x < 256) {
        const int idx = blockIdx.x * 256 + t;
        const int a = idx >> 12, b = (idx >> 8) & 15,
                  c = (idx >> 4) & 15, d = idx & 15;
#define GIDX(x, y, zz, w) d_gbuf[((x) << 12) | ((y) << 8) | ((zz) << 4) | (w)]
        float s = GIDX(a, b, c, d) + GIDX(b, a, c, d)
                + GIDX(a, b, d, c) + GIDX(b, a, d, c)
                + GIDX(c, d, a, b) + GIDX(d, c, a, b)
                + GIDX(c, d, b, a) + GIDX(d, c, b, a);
#undef GIDX
        out[256 + idx] = 0.125f * s;
    } else {
        if (t < NZ) d_hist[t] = 0;          // reset for next graph replay
    }
}

// ---------------------------------------------------------------------------
// Inputs (metadata order): Z, pos, ghost, embed, W_tp, w_h, b_h, w_g, b_g.
// pos and ghost are dead code in the reference -- never touched.
// ---------------------------------------------------------------------------
extern "C" void kernel_launch(void* const* d_in, const int* in_sizes, int n_in,
                              void* d_out, int out_size) {
    const int*   Z     = (const int*)d_in[0];
    const float* embed = (const float*)d_in[3];
    const float* W_tp  = (const float*)d_in[4];
    const float* w_h   = (const float*)d_in[5];
    const float* b_h   = (const float*)d_in[6];
    const float* w_g   = (const float*)d_in[7];
    const float* b_g   = (const float*)d_in[8];
    float* out = (float*)d_out;
    const int n = in_sizes[0];

    kA<<<GRIDA, 256>>>(Z, n, embed, W_tp);
    kB<<<GRIDB, 256>>>(w_g, b_g, w_h, b_h, out);
}